// round 2
// baseline (speedup 1.0000x reference)
#include <cuda_runtime.h>
#include <math.h>

// Problem constants
#define B_  2
#define T_  2048
#define C_  1024
#define H_  16
#define D_  64
#define M_  (B_ * T_)        // 4096 rows
#define QKV_N (3 * C_)       // 3072

// Scratch (allocation-free rule: __device__ globals)
__device__ float g_qkv[(size_t)M_ * QKV_N];   // [B,T,3C]  ~50 MB
__device__ float g_attn[(size_t)M_ * C_];     // [B,T,C]   ~17 MB

// ---------------------------------------------------------------------------
// Generic tiled fp32 GEMM with bias: C[M,N] = A[M,K] @ Bm[K,N] + bias[N]
// BM=BN=64, BK=16, 256 threads, 4x4 register tile per thread.
// M,N divisible by 64; K divisible by 16 (true for all our shapes).
// ---------------------------------------------------------------------------
__global__ void gemm_bias_kernel(const float* __restrict__ A,
                                 const float* __restrict__ Bm,
                                 const float* __restrict__ bias,
                                 float* __restrict__ Cm,
                                 int M, int N, int K) {
    const int BM = 64, BN = 64, BK = 16;
    __shared__ float As[BK][BM + 1];
    __shared__ float Bs[BK][BN + 1];

    int tid = threadIdx.x;          // 0..255
    int tx = tid & 15, ty = tid >> 4;
    int brow = blockIdx.y * BM;
    int bcol = blockIdx.x * BN;

    float acc[4][4] = {};

    for (int k0 = 0; k0 < K; k0 += BK) {
        #pragma unroll
        for (int i = 0; i < 4; i++) {
            int idx = tid + i * 256;            // 0..1023
            int m  = idx >> 4, k  = idx & 15;   // A tile
            As[k][m] = A[(size_t)(brow + m) * K + k0 + k];
            int kb = idx >> 6, n  = idx & 63;   // B tile (coalesced on n)
            Bs[kb][n] = Bm[(size_t)(k0 + kb) * N + bcol + n];
        }
        __syncthreads();

        #pragma unroll
        for (int k = 0; k < BK; k++) {
            float a[4], b[4];
            #pragma unroll
            for (int i = 0; i < 4; i++) a[i] = As[k][ty * 4 + i];
            #pragma unroll
            for (int j = 0; j < 4; j++) b[j] = Bs[k][tx * 4 + j];
            #pragma unroll
            for (int i = 0; i < 4; i++)
                #pragma unroll
                for (int j = 0; j < 4; j++)
                    acc[i][j] += a[i] * b[j];
        }
        __syncthreads();
    }

    #pragma unroll
    for (int i = 0; i < 4; i++) {
        int m = brow + ty * 4 + i;
        #pragma unroll
        for (int j = 0; j < 4; j++) {
            int n = bcol + tx * 4 + j;
            Cm[(size_t)m * N + n] = acc[i][j] + bias[n];
        }
    }
}

// ---------------------------------------------------------------------------
// Flash attention (causal). One block = (batch b, head h, 64-query tile).
// Reads Q/K/V straight out of g_qkv [B,T,3C]; writes O to g_attn [B,T,C].
// 256 threads; Q/K/V/S tiles (64x64) in dynamic smem; online softmax.
// ---------------------------------------------------------------------------
#define SROW 65   // padded row stride for smem tiles
#define ATTN_SMEM_FLOATS (4 * 64 * SROW + 3 * 64)
#define ATTN_SMEM_BYTES  (ATTN_SMEM_FLOATS * 4)

__global__ void attn_kernel(const float* __restrict__ qkv,
                            float* __restrict__ out) {
    int qt = blockIdx.x;    // query tile 0..31
    int h  = blockIdx.y;    // head
    int b  = blockIdx.z;    // batch

    extern __shared__ float sm[];
    float* Qs = sm;                     // 64 x SROW
    float* Ks = Qs + 64 * SROW;
    float* Vs = Ks + 64 * SROW;
    float* Ss = Vs + 64 * SROW;
    float* mS = Ss + 64 * SROW;         // 64
    float* lS = mS + 64;                // 64
    float* aS = lS + 64;                // 64 (alpha per row)

    int tid = threadIdx.x;              // 0..255
    int tx = tid & 15, ty = tid >> 4;

    const float scale = 0.125f;         // 1/sqrt(64)
    const int rowStride = QKV_N;        // 3072 floats per token
    const float* base = qkv + (size_t)b * T_ * rowStride;
    int q0 = qt * 64;
    int hoff = h * D_;

    // Load Q tile (scale folded in)
    for (int i = tid; i < 64 * 64; i += 256) {
        int r = i >> 6, d = i & 63;
        Qs[r * SROW + d] = base[(size_t)(q0 + r) * rowStride + hoff + d] * scale;
    }
    if (tid < 64) { mS[tid] = -INFINITY; lS[tid] = 0.f; }

    float acc[4][4] = {};               // O: rows ty*4+i, dims tx*4+j
    __syncthreads();

    for (int kt = 0; kt <= qt; kt++) {
        int k0 = kt * 64;
        // Load K and V tiles
        for (int i = tid; i < 64 * 64; i += 256) {
            int r = i >> 6, d = i & 63;
            size_t rowbase = (size_t)(k0 + r) * rowStride;
            Ks[r * SROW + d] = base[rowbase + C_      + hoff + d];
            Vs[r * SROW + d] = base[rowbase + 2 * C_  + hoff + d];
        }
        __syncthreads();

        // S = Q @ K^T  (64x64x64)
        float s[4][4] = {};
        #pragma unroll 16
        for (int d = 0; d < 64; d++) {
            float a[4], bb[4];
            #pragma unroll
            for (int i = 0; i < 4; i++) a[i]  = Qs[(ty * 4 + i) * SROW + d];
            #pragma unroll
            for (int j = 0; j < 4; j++) bb[j] = Ks[(tx * 4 + j) * SROW + d];
            #pragma unroll
            for (int i = 0; i < 4; i++)
                #pragma unroll
                for (int j = 0; j < 4; j++)
                    s[i][j] += a[i] * bb[j];
        }
        // Causal mask only on diagonal tile, then stage S
        bool diag = (kt == qt);
        #pragma unroll
        for (int i = 0; i < 4; i++) {
            int qr = ty * 4 + i;
            #pragma unroll
            for (int j = 0; j < 4; j++) {
                int kc = tx * 4 + j;
                float v = s[i][j];
                if (diag && kc > qr) v = -INFINITY;
                Ss[qr * SROW + kc] = v;
            }
        }
        __syncthreads();

        // Online softmax: 4 threads per row (lanes t, row = t>>2, seg = t&3)
        {
            int row = tid >> 2, seg = tid & 3;
            float pm = -INFINITY;
            #pragma unroll
            for (int c = 0; c < 16; c++)
                pm = fmaxf(pm, Ss[row * SROW + seg * 16 + c]);
            pm = fmaxf(pm, __shfl_xor_sync(0xffffffff, pm, 1));
            pm = fmaxf(pm, __shfl_xor_sync(0xffffffff, pm, 2));

            float mOld = mS[row];
            float mNew = fmaxf(mOld, pm);
            float al   = __expf(mOld - mNew);
            float psum = 0.f;
            #pragma unroll
            for (int c = 0; c < 16; c++) {
                float p = __expf(Ss[row * SROW + seg * 16 + c] - mNew);
                Ss[row * SROW + seg * 16 + c] = p;
                psum += p;
            }
            psum += __shfl_xor_sync(0xffffffff, psum, 1);
            psum += __shfl_xor_sync(0xffffffff, psum, 2);
            if (seg == 0) {
                mS[row] = mNew;
                lS[row] = lS[row] * al + psum;
                aS[row] = al;
            }
        }
        __syncthreads();

        // O = O*alpha + P @ V  (64x64x64)
        float alr[4];
        #pragma unroll
        for (int i = 0; i < 4; i++) alr[i] = aS[ty * 4 + i];
        #pragma unroll
        for (int i = 0; i < 4; i++)
            #pragma unroll
            for (int j = 0; j < 4; j++)
                acc[i][j] *= alr[i];

        #pragma unroll 16
        for (int k = 0; k < 64; k++) {
            float p[4], vv[4];
            #pragma unroll
            for (int i = 0; i < 4; i++) p[i]  = Ss[(ty * 4 + i) * SROW + k];
            #pragma unroll
            for (int j = 0; j < 4; j++) vv[j] = Vs[k * SROW + tx * 4 + j];
            #pragma unroll
            for (int i = 0; i < 4; i++)
                #pragma unroll
                for (int j = 0; j < 4; j++)
                    acc[i][j] += p[i] * vv[j];
        }
        __syncthreads();
    }

    // Normalize and store O -> g_attn [B,T,C]
    #pragma unroll
    for (int i = 0; i < 4; i++) {
        int qr = ty * 4 + i;
        float inv = 1.0f / lS[qr];
        #pragma unroll
        for (int j = 0; j < 4; j++) {
            out[((size_t)b * T_ + q0 + qr) * C_ + hoff + tx * 4 + j] =
                acc[i][j] * inv;
        }
    }
}

// ---------------------------------------------------------------------------
extern "C" void kernel_launch(void* const* d_in, const int* in_sizes, int n_in,
                              void* d_out, int out_size) {
    const float* x     = (const float*)d_in[0];   // [B,T,C]
    const float* Wqkv  = (const float*)d_in[1];   // [C,3C]
    const float* bqkv  = (const float*)d_in[2];   // [3C]
    const float* Wproj = (const float*)d_in[3];   // [C,C]
    const float* bproj = (const float*)d_in[4];   // [C]
    float* out = (float*)d_out;                   // [B,T,C]

    float* qkv  = nullptr;
    float* attn = nullptr;
    cudaGetSymbolAddress((void**)&qkv,  g_qkv);
    cudaGetSymbolAddress((void**)&attn, g_attn);

    cudaFuncSetAttribute(attn_kernel,
                         cudaFuncAttributeMaxDynamicSharedMemorySize,
                         ATTN_SMEM_BYTES);

    // 1) QKV projection: [4096,1024] @ [1024,3072] + bias
    {
        dim3 grid(QKV_N / 64, M_ / 64);
        gemm_bias_kernel<<<grid, 256>>>(x, Wqkv, bqkv, qkv, M_, QKV_N, C_);
    }
    // 2) Causal flash attention per (q-tile, head, batch)
    {
        dim3 grid(T_ / 64, H_, B_);
        attn_kernel<<<grid, 256, ATTN_SMEM_BYTES>>>(qkv, attn);
    }
    // 3) Output projection: [4096,1024] @ [1024,1024] + bias
    {
        dim3 grid(C_ / 64, M_ / 64);
        gemm_bias_kernel<<<grid, 256>>>(attn, Wproj, bproj, out, M_, C_, C_);
    }
}

// round 3
// speedup vs baseline: 1.8136x; 1.8136x over previous
#include <cuda_runtime.h>
#include <math.h>

// Problem constants
#define B_  2
#define T_  2048
#define C_  1024
#define H_  16
#define D_  64
#define M_  (B_ * T_)        // 4096 rows
#define QKV_N (3 * C_)       // 3072

// Scratch (allocation-free rule: __device__ globals)
__device__ float g_qkv[(size_t)M_ * QKV_N];   // [B,T,3C]
__device__ float g_attn[(size_t)M_ * C_];     // [B,T,C]

// ---------------------------------------------------------------------------
// TF32 tensor-core GEMM with bias: C[M,N] = A[M,K] @ Bm[K,N] + bias[N]
// BM=BN=128, BK=16; 256 threads = 8 warps in 2x4 (row x col) layout;
// each warp computes 64x32 via 4x4 tiles of mma.m16n8k8.tf32.
// Requires M%128==0, N%128==0, K%16==0 (true for all shapes here).
// ---------------------------------------------------------------------------
__device__ __forceinline__ unsigned f2tf32(float f) {
    unsigned u;
    asm("cvt.rna.tf32.f32 %0, %1;" : "=r"(u) : "f"(f));
    return u;
}

__global__ __launch_bounds__(256) void gemm_tf32_kernel(
        const float* __restrict__ A,
        const float* __restrict__ Bm,
        const float* __restrict__ bias,
        float* __restrict__ Cm,
        int M, int N, int K) {
    // Strides chosen for conflict-free fragment loads:
    //  A stride 20: banks (20*row + k) % 32 cover all 32 for row 0..7 x k 0..3
    //  B stride 136: banks (136*k + col) % 32 = (8k + col) distinct for k 0..3 x col 0..7
    __shared__ unsigned As[128][20];
    __shared__ unsigned Bs[16][136];

    const int tid  = threadIdx.x;
    const int lane = tid & 31;
    const int warp = tid >> 5;
    const int warpRow = warp >> 2;      // 0..1 (64 rows each)
    const int warpCol = warp & 3;       // 0..3 (32 cols each)
    const int group = lane >> 2;        // 0..7
    const int tid4  = lane & 3;         // 0..3

    const int brow = blockIdx.y * 128;
    const int bcol = blockIdx.x * 128;

    float acc[4][4][4];                 // [mt][nt][reg]
    #pragma unroll
    for (int i = 0; i < 4; i++)
        #pragma unroll
        for (int j = 0; j < 4; j++)
            #pragma unroll
            for (int r = 0; r < 4; r++) acc[i][j][r] = 0.f;

    for (int k0 = 0; k0 < K; k0 += 16) {
        // ---- load tiles (vectorized global, tf32-converted into smem) ----
        #pragma unroll
        for (int i = 0; i < 2; i++) {
            int idx = tid + i * 256;                    // 0..511
            {   // A tile: 128 rows x 16 k -> 512 float4
                int row = idx >> 2, kq = idx & 3;
                float4 v = *reinterpret_cast<const float4*>(
                    &A[(size_t)(brow + row) * K + k0 + kq * 4]);
                As[row][kq * 4 + 0] = f2tf32(v.x);
                As[row][kq * 4 + 1] = f2tf32(v.y);
                As[row][kq * 4 + 2] = f2tf32(v.z);
                As[row][kq * 4 + 3] = f2tf32(v.w);
            }
            {   // B tile: 16 k x 128 cols -> 512 float4
                int kb = idx >> 5, cq = idx & 31;
                float4 v = *reinterpret_cast<const float4*>(
                    &Bm[(size_t)(k0 + kb) * N + bcol + cq * 4]);
                Bs[kb][cq * 4 + 0] = f2tf32(v.x);
                Bs[kb][cq * 4 + 1] = f2tf32(v.y);
                Bs[kb][cq * 4 + 2] = f2tf32(v.z);
                Bs[kb][cq * 4 + 3] = f2tf32(v.w);
            }
        }
        __syncthreads();

        // ---- 2 k-steps of 8 ----
        #pragma unroll
        for (int ks = 0; ks < 2; ks++) {
            int k = ks * 8;
            unsigned a[4][4];
            #pragma unroll
            for (int mt = 0; mt < 4; mt++) {
                int row = warpRow * 64 + mt * 16 + group;
                a[mt][0] = As[row    ][k + tid4    ];
                a[mt][1] = As[row + 8][k + tid4    ];
                a[mt][2] = As[row    ][k + tid4 + 4];
                a[mt][3] = As[row + 8][k + tid4 + 4];
            }
            unsigned b[4][2];
            #pragma unroll
            for (int nt = 0; nt < 4; nt++) {
                int col = warpCol * 32 + nt * 8 + group;
                b[nt][0] = Bs[k + tid4    ][col];
                b[nt][1] = Bs[k + tid4 + 4][col];
            }
            #pragma unroll
            for (int mt = 0; mt < 4; mt++)
                #pragma unroll
                for (int nt = 0; nt < 4; nt++) {
                    asm volatile(
                        "mma.sync.aligned.m16n8k8.row.col.f32.tf32.tf32.f32 "
                        "{%0,%1,%2,%3},{%4,%5,%6,%7},{%8,%9},{%0,%1,%2,%3};"
                        : "+f"(acc[mt][nt][0]), "+f"(acc[mt][nt][1]),
                          "+f"(acc[mt][nt][2]), "+f"(acc[mt][nt][3])
                        : "r"(a[mt][0]), "r"(a[mt][1]),
                          "r"(a[mt][2]), "r"(a[mt][3]),
                          "r"(b[nt][0]), "r"(b[nt][1]));
                }
        }
        __syncthreads();
    }

    // ---- epilogue: D fragment layout -> global, + bias ----
    #pragma unroll
    for (int mt = 0; mt < 4; mt++) {
        int m0 = brow + warpRow * 64 + mt * 16 + group;
        #pragma unroll
        for (int nt = 0; nt < 4; nt++) {
            int n0 = bcol + warpCol * 32 + nt * 8 + tid4 * 2;
            Cm[(size_t)m0 * N + n0    ] = acc[mt][nt][0] + bias[n0];
            Cm[(size_t)m0 * N + n0 + 1] = acc[mt][nt][1] + bias[n0 + 1];
            Cm[(size_t)(m0 + 8) * N + n0    ] = acc[mt][nt][2] + bias[n0];
            Cm[(size_t)(m0 + 8) * N + n0 + 1] = acc[mt][nt][3] + bias[n0 + 1];
        }
    }
}

// ---------------------------------------------------------------------------
// Flash attention (causal). One block = (batch b, head h, 64-query tile).
// Unchanged from R1 (correct anchor; attacked next round).
// ---------------------------------------------------------------------------
#define SROW 65
#define ATTN_SMEM_FLOATS (4 * 64 * SROW + 3 * 64)
#define ATTN_SMEM_BYTES  (ATTN_SMEM_FLOATS * 4)

__global__ void attn_kernel(const float* __restrict__ qkv,
                            float* __restrict__ out) {
    int qt = blockIdx.x;
    int h  = blockIdx.y;
    int b  = blockIdx.z;

    extern __shared__ float sm[];
    float* Qs = sm;
    float* Ks = Qs + 64 * SROW;
    float* Vs = Ks + 64 * SROW;
    float* Ss = Vs + 64 * SROW;
    float* mS = Ss + 64 * SROW;
    float* lS = mS + 64;
    float* aS = lS + 64;

    int tid = threadIdx.x;
    int tx = tid & 15, ty = tid >> 4;

    const float scale = 0.125f;
    const int rowStride = QKV_N;
    const float* base = qkv + (size_t)b * T_ * rowStride;
    int q0 = qt * 64;
    int hoff = h * D_;

    for (int i = tid; i < 64 * 64; i += 256) {
        int r = i >> 6, d = i & 63;
        Qs[r * SROW + d] = base[(size_t)(q0 + r) * rowStride + hoff + d] * scale;
    }
    if (tid < 64) { mS[tid] = -INFINITY; lS[tid] = 0.f; }

    float acc[4][4] = {};
    __syncthreads();

    for (int kt = 0; kt <= qt; kt++) {
        int k0 = kt * 64;
        for (int i = tid; i < 64 * 64; i += 256) {
            int r = i >> 6, d = i & 63;
            size_t rowbase = (size_t)(k0 + r) * rowStride;
            Ks[r * SROW + d] = base[rowbase + C_     + hoff + d];
            Vs[r * SROW + d] = base[rowbase + 2 * C_ + hoff + d];
        }
        __syncthreads();

        float s[4][4] = {};
        #pragma unroll 16
        for (int d = 0; d < 64; d++) {
            float a[4], bb[4];
            #pragma unroll
            for (int i = 0; i < 4; i++) a[i]  = Qs[(ty * 4 + i) * SROW + d];
            #pragma unroll
            for (int j = 0; j < 4; j++) bb[j] = Ks[(tx * 4 + j) * SROW + d];
            #pragma unroll
            for (int i = 0; i < 4; i++)
                #pragma unroll
                for (int j = 0; j < 4; j++)
                    s[i][j] += a[i] * bb[j];
        }
        bool diag = (kt == qt);
        #pragma unroll
        for (int i = 0; i < 4; i++) {
            int qr = ty * 4 + i;
            #pragma unroll
            for (int j = 0; j < 4; j++) {
                int kc = tx * 4 + j;
                float v = s[i][j];
                if (diag && kc > qr) v = -INFINITY;
                Ss[qr * SROW + kc] = v;
            }
        }
        __syncthreads();

        {
            int row = tid >> 2, seg = tid & 3;
            float pm = -INFINITY;
            #pragma unroll
            for (int c = 0; c < 16; c++)
                pm = fmaxf(pm, Ss[row * SROW + seg * 16 + c]);
            pm = fmaxf(pm, __shfl_xor_sync(0xffffffff, pm, 1));
            pm = fmaxf(pm, __shfl_xor_sync(0xffffffff, pm, 2));

            float mOld = mS[row];
            float mNew = fmaxf(mOld, pm);
            float al   = __expf(mOld - mNew);
            float psum = 0.f;
            #pragma unroll
            for (int c = 0; c < 16; c++) {
                float p = __expf(Ss[row * SROW + seg * 16 + c] - mNew);
                Ss[row * SROW + seg * 16 + c] = p;
                psum += p;
            }
            psum += __shfl_xor_sync(0xffffffff, psum, 1);
            psum += __shfl_xor_sync(0xffffffff, psum, 2);
            if (seg == 0) {
                mS[row] = mNew;
                lS[row] = lS[row] * al + psum;
                aS[row] = al;
            }
        }
        __syncthreads();

        float alr[4];
        #pragma unroll
        for (int i = 0; i < 4; i++) alr[i] = aS[ty * 4 + i];
        #pragma unroll
        for (int i = 0; i < 4; i++)
            #pragma unroll
            for (int j = 0; j < 4; j++)
                acc[i][j] *= alr[i];

        #pragma unroll 16
        for (int k = 0; k < 64; k++) {
            float p[4], vv[4];
            #pragma unroll
            for (int i = 0; i < 4; i++) p[i]  = Ss[(ty * 4 + i) * SROW + k];
            #pragma unroll
            for (int j = 0; j < 4; j++) vv[j] = Vs[k * SROW + tx * 4 + j];
            #pragma unroll
            for (int i = 0; i < 4; i++)
                #pragma unroll
                for (int j = 0; j < 4; j++)
                    acc[i][j] += p[i] * vv[j];
        }
        __syncthreads();
    }

    #pragma unroll
    for (int i = 0; i < 4; i++) {
        int qr = ty * 4 + i;
        float inv = 1.0f / lS[qr];
        #pragma unroll
        for (int j = 0; j < 4; j++) {
            out[((size_t)b * T_ + q0 + qr) * C_ + hoff + tx * 4 + j] =
                acc[i][j] * inv;
        }
    }
}

// ---------------------------------------------------------------------------
extern "C" void kernel_launch(void* const* d_in, const int* in_sizes, int n_in,
                              void* d_out, int out_size) {
    const float* x     = (const float*)d_in[0];
    const float* Wqkv  = (const float*)d_in[1];
    const float* bqkv  = (const float*)d_in[2];
    const float* Wproj = (const float*)d_in[3];
    const float* bproj = (const float*)d_in[4];
    float* out = (float*)d_out;

    float* qkv  = nullptr;
    float* attn = nullptr;
    cudaGetSymbolAddress((void**)&qkv,  g_qkv);
    cudaGetSymbolAddress((void**)&attn, g_attn);

    cudaFuncSetAttribute(attn_kernel,
                         cudaFuncAttributeMaxDynamicSharedMemorySize,
                         ATTN_SMEM_BYTES);

    // 1) QKV projection (tf32 tensor cores): [4096,1024]@[1024,3072]+bias
    {
        dim3 grid(QKV_N / 128, M_ / 128);
        gemm_tf32_kernel<<<grid, 256>>>(x, Wqkv, bqkv, qkv, M_, QKV_N, C_);
    }
    // 2) Causal flash attention
    {
        dim3 grid(T_ / 64, H_, B_);
        attn_kernel<<<grid, 256, ATTN_SMEM_BYTES>>>(qkv, attn);
    }
    // 3) Output projection (tf32 tensor cores): [4096,1024]@[1024,1024]+bias
    {
        dim3 grid(C_ / 128, M_ / 128);
        gemm_tf32_kernel<<<grid, 256>>>(attn, Wproj, bproj, out, M_, C_, C_);
    }
}

// round 4
// speedup vs baseline: 3.1721x; 1.7491x over previous
#include <cuda_runtime.h>
#include <math.h>

// Problem constants
#define B_  2
#define T_  2048
#define C_  1024
#define H_  16
#define D_  64
#define M_  (B_ * T_)        // 4096 rows
#define QKV_N (3 * C_)       // 3072

// Scratch (allocation-free rule: __device__ globals)
__device__ float g_qkv[(size_t)M_ * QKV_N];   // [B,T,3C]
__device__ float g_attn[(size_t)M_ * C_];     // [B,T,C]

__device__ __forceinline__ unsigned f2tf32(float f) {
    unsigned u;
    asm("cvt.rna.tf32.f32 %0, %1;" : "=r"(u) : "f"(f));
    return u;
}

// ---------------------------------------------------------------------------
// TF32 tensor-core GEMM with bias (unchanged from R2; validated).
// ---------------------------------------------------------------------------
__global__ __launch_bounds__(256) void gemm_tf32_kernel(
        const float* __restrict__ A,
        const float* __restrict__ Bm,
        const float* __restrict__ bias,
        float* __restrict__ Cm,
        int M, int N, int K) {
    __shared__ unsigned As[128][20];
    __shared__ unsigned Bs[16][136];

    const int tid  = threadIdx.x;
    const int lane = tid & 31;
    const int warp = tid >> 5;
    const int warpRow = warp >> 2;
    const int warpCol = warp & 3;
    const int group = lane >> 2;
    const int tid4  = lane & 3;

    const int brow = blockIdx.y * 128;
    const int bcol = blockIdx.x * 128;

    float acc[4][4][4];
    #pragma unroll
    for (int i = 0; i < 4; i++)
        #pragma unroll
        for (int j = 0; j < 4; j++)
            #pragma unroll
            for (int r = 0; r < 4; r++) acc[i][j][r] = 0.f;

    for (int k0 = 0; k0 < K; k0 += 16) {
        #pragma unroll
        for (int i = 0; i < 2; i++) {
            int idx = tid + i * 256;
            {
                int row = idx >> 2, kq = idx & 3;
                float4 v = *reinterpret_cast<const float4*>(
                    &A[(size_t)(brow + row) * K + k0 + kq * 4]);
                As[row][kq * 4 + 0] = f2tf32(v.x);
                As[row][kq * 4 + 1] = f2tf32(v.y);
                As[row][kq * 4 + 2] = f2tf32(v.z);
                As[row][kq * 4 + 3] = f2tf32(v.w);
            }
            {
                int kb = idx >> 5, cq = idx & 31;
                float4 v = *reinterpret_cast<const float4*>(
                    &Bm[(size_t)(k0 + kb) * N + bcol + cq * 4]);
                Bs[kb][cq * 4 + 0] = f2tf32(v.x);
                Bs[kb][cq * 4 + 1] = f2tf32(v.y);
                Bs[kb][cq * 4 + 2] = f2tf32(v.z);
                Bs[kb][cq * 4 + 3] = f2tf32(v.w);
            }
        }
        __syncthreads();

        #pragma unroll
        for (int ks = 0; ks < 2; ks++) {
            int k = ks * 8;
            unsigned a[4][4];
            #pragma unroll
            for (int mt = 0; mt < 4; mt++) {
                int row = warpRow * 64 + mt * 16 + group;
                a[mt][0] = As[row    ][k + tid4    ];
                a[mt][1] = As[row + 8][k + tid4    ];
                a[mt][2] = As[row    ][k + tid4 + 4];
                a[mt][3] = As[row + 8][k + tid4 + 4];
            }
            unsigned b[4][2];
            #pragma unroll
            for (int nt = 0; nt < 4; nt++) {
                int col = warpCol * 32 + nt * 8 + group;
                b[nt][0] = Bs[k + tid4    ][col];
                b[nt][1] = Bs[k + tid4 + 4][col];
            }
            #pragma unroll
            for (int mt = 0; mt < 4; mt++)
                #pragma unroll
                for (int nt = 0; nt < 4; nt++) {
                    asm volatile(
                        "mma.sync.aligned.m16n8k8.row.col.f32.tf32.tf32.f32 "
                        "{%0,%1,%2,%3},{%4,%5,%6,%7},{%8,%9},{%0,%1,%2,%3};"
                        : "+f"(acc[mt][nt][0]), "+f"(acc[mt][nt][1]),
                          "+f"(acc[mt][nt][2]), "+f"(acc[mt][nt][3])
                        : "r"(a[mt][0]), "r"(a[mt][1]),
                          "r"(a[mt][2]), "r"(a[mt][3]),
                          "r"(b[nt][0]), "r"(b[nt][1]));
                }
        }
        __syncthreads();
    }

    #pragma unroll
    for (int mt = 0; mt < 4; mt++) {
        int m0 = brow + warpRow * 64 + mt * 16 + group;
        #pragma unroll
        for (int nt = 0; nt < 4; nt++) {
            int n0 = bcol + warpCol * 32 + nt * 8 + tid4 * 2;
            Cm[(size_t)m0 * N + n0    ] = acc[mt][nt][0] + bias[n0];
            Cm[(size_t)m0 * N + n0 + 1] = acc[mt][nt][1] + bias[n0 + 1];
            Cm[(size_t)(m0 + 8) * N + n0    ] = acc[mt][nt][2] + bias[n0];
            Cm[(size_t)(m0 + 8) * N + n0 + 1] = acc[mt][nt][3] + bias[n0 + 1];
        }
    }
}

// ---------------------------------------------------------------------------
// Tensor-core flash attention (causal, tf32 mma).
// Block = (q-tile 64, head, batch); 128 threads = 4 warps, 16 Q-rows each.
// S = Q@K^T in registers -> online softmax in fragment layout -> P to smem
// (per-warp slice) -> O += P@V. Smem stride 68 => conflict-free fragments.
// ---------------------------------------------------------------------------
#define AST 68
#define ATTN_SMEM_BYTES (4 * 64 * AST * 4)   // Qs, Ks, Vs, Ps

__global__ __launch_bounds__(128) void attn_tc_kernel(
        const float* __restrict__ qkv,
        float* __restrict__ out) {
    int qt = blockIdx.x;
    int h  = blockIdx.y;
    int b  = blockIdx.z;

    extern __shared__ unsigned smu[];
    unsigned* Qs = smu;
    unsigned* Ks = Qs + 64 * AST;
    unsigned* Vs = Ks + 64 * AST;
    unsigned* Ps = Vs + 64 * AST;

    const int tid  = threadIdx.x;
    const int lane = tid & 31;
    const int warp = tid >> 5;
    const int g = lane >> 2;      // 0..7
    const int t = lane & 3;       // 0..3
    const int m0 = warp * 16;     // warp's Q-row base within tile

    const float scale = 0.125f;
    const float* base = qkv + (size_t)b * T_ * QKV_N;
    const int q0 = qt * 64;
    const int hoff = h * D_;

    // Load Q tile (scale folded, tf32). 64 rows x 16 float4 = 1024 quads.
    for (int i = tid; i < 64 * 16; i += 128) {
        int r = i >> 4, q = i & 15;
        float4 v = *reinterpret_cast<const float4*>(
            &base[(size_t)(q0 + r) * QKV_N + hoff + q * 4]);
        unsigned* dst = &Qs[r * AST + q * 4];
        dst[0] = f2tf32(v.x * scale);
        dst[1] = f2tf32(v.y * scale);
        dst[2] = f2tf32(v.z * scale);
        dst[3] = f2tf32(v.w * scale);
    }

    float o[8][4];                 // O: 8 d-tiles of m16n8
    #pragma unroll
    for (int d = 0; d < 8; d++)
        #pragma unroll
        for (int r = 0; r < 4; r++) o[d][r] = 0.f;
    float mRow[2] = {-INFINITY, -INFINITY};
    float lRow[2] = {0.f, 0.f};

    __syncthreads();

    for (int kt = 0; kt <= qt; kt++) {
        int k0 = kt * 64;
        // Load K, V tiles (tf32)
        for (int i = tid; i < 64 * 16; i += 128) {
            int r = i >> 4, q = i & 15;
            size_t rowbase = (size_t)(k0 + r) * QKV_N + hoff + q * 4;
            float4 kv = *reinterpret_cast<const float4*>(&base[rowbase + C_]);
            float4 vv = *reinterpret_cast<const float4*>(&base[rowbase + 2 * C_]);
            unsigned* dk = &Ks[r * AST + q * 4];
            dk[0] = f2tf32(kv.x); dk[1] = f2tf32(kv.y);
            dk[2] = f2tf32(kv.z); dk[3] = f2tf32(kv.w);
            unsigned* dv = &Vs[r * AST + q * 4];
            dv[0] = f2tf32(vv.x); dv[1] = f2tf32(vv.y);
            dv[2] = f2tf32(vv.z); dv[3] = f2tf32(vv.w);
        }
        __syncthreads();

        // ---- S = Q @ K^T : 8 k-steps x 8 n-tiles of m16n8k8 ----
        float s[8][4];
        #pragma unroll
        for (int n = 0; n < 8; n++)
            #pragma unroll
            for (int r = 0; r < 4; r++) s[n][r] = 0.f;

        #pragma unroll
        for (int kk = 0; kk < 8; kk++) {
            unsigned a0 = Qs[(m0 + g    ) * AST + kk * 8 + t    ];
            unsigned a1 = Qs[(m0 + g + 8) * AST + kk * 8 + t    ];
            unsigned a2 = Qs[(m0 + g    ) * AST + kk * 8 + t + 4];
            unsigned a3 = Qs[(m0 + g + 8) * AST + kk * 8 + t + 4];
            #pragma unroll
            for (int n = 0; n < 8; n++) {
                unsigned b0 = Ks[(n * 8 + g) * AST + kk * 8 + t    ];
                unsigned b1 = Ks[(n * 8 + g) * AST + kk * 8 + t + 4];
                asm volatile(
                    "mma.sync.aligned.m16n8k8.row.col.f32.tf32.tf32.f32 "
                    "{%0,%1,%2,%3},{%4,%5,%6,%7},{%8,%9},{%0,%1,%2,%3};"
                    : "+f"(s[n][0]), "+f"(s[n][1]), "+f"(s[n][2]), "+f"(s[n][3])
                    : "r"(a0), "r"(a1), "r"(a2), "r"(a3), "r"(b0), "r"(b1));
            }
        }

        // ---- causal mask on diagonal tile ----
        if (kt == qt) {
            #pragma unroll
            for (int n = 0; n < 8; n++) {
                int c0 = n * 8 + 2 * t;
                int r0 = m0 + g, r1 = m0 + g + 8;
                if (c0     > r0) s[n][0] = -INFINITY;
                if (c0 + 1 > r0) s[n][1] = -INFINITY;
                if (c0     > r1) s[n][2] = -INFINITY;
                if (c0 + 1 > r1) s[n][3] = -INFINITY;
            }
        }

        // ---- online softmax (per row-half; rows g and g+8) ----
        #pragma unroll
        for (int half = 0; half < 2; half++) {
            float pm = -INFINITY;
            #pragma unroll
            for (int n = 0; n < 8; n++) {
                pm = fmaxf(pm, s[n][2 * half]);
                pm = fmaxf(pm, s[n][2 * half + 1]);
            }
            pm = fmaxf(pm, __shfl_xor_sync(0xffffffff, pm, 1));
            pm = fmaxf(pm, __shfl_xor_sync(0xffffffff, pm, 2));

            float mNew = fmaxf(mRow[half], pm);
            float alpha = __expf(mRow[half] - mNew);
            float lsum = 0.f;
            #pragma unroll
            for (int n = 0; n < 8; n++) {
                float p0 = __expf(s[n][2 * half    ] - mNew);
                float p1 = __expf(s[n][2 * half + 1] - mNew);
                s[n][2 * half    ] = p0;
                s[n][2 * half + 1] = p1;
                lsum += p0 + p1;
            }
            lsum += __shfl_xor_sync(0xffffffff, lsum, 1);
            lsum += __shfl_xor_sync(0xffffffff, lsum, 2);
            mRow[half] = mNew;
            lRow[half] = lRow[half] * alpha + lsum;
            #pragma unroll
            for (int n = 0; n < 8; n++) {
                o[n][2 * half    ] *= alpha;
                o[n][2 * half + 1] *= alpha;
            }
        }

        // ---- write P (tf32) to this warp's private 16-row slice ----
        #pragma unroll
        for (int n = 0; n < 8; n++) {
            int c = n * 8 + 2 * t;
            Ps[(m0 + g    ) * AST + c    ] = f2tf32(s[n][0]);
            Ps[(m0 + g    ) * AST + c + 1] = f2tf32(s[n][1]);
            Ps[(m0 + g + 8) * AST + c    ] = f2tf32(s[n][2]);
            Ps[(m0 + g + 8) * AST + c + 1] = f2tf32(s[n][3]);
        }
        __syncwarp();

        // ---- O += P @ V : 8 k-steps x 8 d-tiles ----
        #pragma unroll
        for (int kk = 0; kk < 8; kk++) {
            unsigned a0 = Ps[(m0 + g    ) * AST + kk * 8 + t    ];
            unsigned a1 = Ps[(m0 + g + 8) * AST + kk * 8 + t    ];
            unsigned a2 = Ps[(m0 + g    ) * AST + kk * 8 + t + 4];
            unsigned a3 = Ps[(m0 + g + 8) * AST + kk * 8 + t + 4];
            #pragma unroll
            for (int d = 0; d < 8; d++) {
                unsigned b0 = Vs[(kk * 8 + t    ) * AST + d * 8 + g];
                unsigned b1 = Vs[(kk * 8 + t + 4) * AST + d * 8 + g];
                asm volatile(
                    "mma.sync.aligned.m16n8k8.row.col.f32.tf32.tf32.f32 "
                    "{%0,%1,%2,%3},{%4,%5,%6,%7},{%8,%9},{%0,%1,%2,%3};"
                    : "+f"(o[d][0]), "+f"(o[d][1]), "+f"(o[d][2]), "+f"(o[d][3])
                    : "r"(a0), "r"(a1), "r"(a2), "r"(a3), "r"(b0), "r"(b1));
            }
        }
        __syncthreads();   // all warps done with Ks/Vs before next load
    }

    // ---- epilogue: normalize and store ----
    #pragma unroll
    for (int half = 0; half < 2; half++) {
        float inv = 1.0f / lRow[half];
        int row = q0 + m0 + g + half * 8;
        #pragma unroll
        for (int d = 0; d < 8; d++) {
            int col = hoff + d * 8 + 2 * t;
            out[((size_t)b * T_ + row) * C_ + col    ] = o[d][2 * half    ] * inv;
            out[((size_t)b * T_ + row) * C_ + col + 1] = o[d][2 * half + 1] * inv;
        }
    }
}

// ---------------------------------------------------------------------------
extern "C" void kernel_launch(void* const* d_in, const int* in_sizes, int n_in,
                              void* d_out, int out_size) {
    const float* x     = (const float*)d_in[0];
    const float* Wqkv  = (const float*)d_in[1];
    const float* bqkv  = (const float*)d_in[2];
    const float* Wproj = (const float*)d_in[3];
    const float* bproj = (const float*)d_in[4];
    float* out = (float*)d_out;

    float* qkv  = nullptr;
    float* attn = nullptr;
    cudaGetSymbolAddress((void**)&qkv,  g_qkv);
    cudaGetSymbolAddress((void**)&attn, g_attn);

    cudaFuncSetAttribute(attn_tc_kernel,
                         cudaFuncAttributeMaxDynamicSharedMemorySize,
                         ATTN_SMEM_BYTES);

    // 1) QKV projection (tf32 tensor cores)
    {
        dim3 grid(QKV_N / 128, M_ / 128);
        gemm_tf32_kernel<<<grid, 256>>>(x, Wqkv, bqkv, qkv, M_, QKV_N, C_);
    }
    // 2) Causal flash attention (tf32 tensor cores)
    {
        dim3 grid(T_ / 64, H_, B_);
        attn_tc_kernel<<<grid, 128, ATTN_SMEM_BYTES>>>(qkv, attn);
    }
    // 3) Output projection (tf32 tensor cores)
    {
        dim3 grid(C_ / 128, M_ / 128);
        gemm_tf32_kernel<<<grid, 256>>>(attn, Wproj, bproj, out, M_, C_, C_);
    }
}